// round 4
// baseline (speedup 1.0000x reference)
#include <cuda_runtime.h>

#define FULLM 0xFFFFFFFFu
#define NQ 10
#define NL 4

// Amp index i in [0,1024), wire q <-> bit (9-q) (wire 0 = MSB).
// 512 threads, 2 amps: i = (k<<9)|tid.
// Layout A: k=wire0; tid bits 8..5 = wires 1..4; lane bits 4..0 = wires 5..9.
// Layout B (after transpose T swapping bit pairs 8<->4,7<->3,6<->2,5<->1):
//   lane bits: b4=wire1, b3=wire2, b2=wire3, b1=wire4, b0=wire9; tid-hi = wires 5..8.

// CNOT-ring gather permutation (GF(2)-linear): new[i] = old[sigma(i)]
__device__ __forceinline__ constexpr int sigma_c(int src) {
  src ^= ((src >> 0) & 1) << 9;  // (9,0)
  src ^= ((src >> 1) & 1) << 0;  // (8,9)
  src ^= ((src >> 2) & 1) << 1;  // (7,8)
  src ^= ((src >> 3) & 1) << 2;  // (6,7)
  src ^= ((src >> 4) & 1) << 3;  // (5,6)
  src ^= ((src >> 5) & 1) << 4;  // (4,5)
  src ^= ((src >> 6) & 1) << 5;  // (3,4)
  src ^= ((src >> 7) & 1) << 6;  // (2,3)
  src ^= ((src >> 8) & 1) << 7;  // (1,2)
  src ^= ((src >> 9) & 1) << 8;  // (0,1)
  return src;
}
// transpose: swap bit pairs (8,4) (7,3) (6,2) (5,1); bits 0,9 fixed. Self-inverse, linear.
__device__ __forceinline__ constexpr int T_c(int x) {
  return (x & 0x201) | ((x & 0x1E) << 4) | ((x >> 4) & 0x1E);
}
// smem bank swizzle (GF(2)-linear, so it composes with XOR offsets)
__device__ __forceinline__ constexpr int swz(int j) { return j ^ ((j >> 5) & 31); }

__global__ void __launch_bounds__(512)
hqh_kernel(const float* __restrict__ x,
           const float* __restrict__ params,
           float* __restrict__ out,
           int nTok)
{
  __shared__ float bufA[1024];   // T-round buffer (layout-A linear, swizzled)
  __shared__ float bufB[1024];   // tau-round buffer (layout-B linear, swizzled)
  __shared__ float pc[NL * NQ], ps[NL * NQ];
  __shared__ float r1[16][17];
  __shared__ float zbs[NQ], xbs[NQ];

  const int tid  = threadIdx.x;
  const int lane = tid & 31;
  const int w    = tid >> 5;     // warp id = wires 1..4 bits (b3=wire1 ... b0=wire4)

  if (tid < NL * NQ) {
    float s, c;
    __sincosf(0.5f * params[tid], &s, &c);
    pc[tid] = c; ps[tid] = s;
  }

  // hoisted address math (all GF(2)-linear maps of tid)
  const int sigTid = sigma_c(tid);
  const int sTid   = swz(tid);                  // store addr (k=1: ^0x210 = swz(0x200))
  const int sT5    = swz(T_c(tid));             // T-gather   (k=1: ^0x210 = swz(T(0x200)))
  const int sTau   = swz(T_c(sigTid));          // tau-gather (k=1: ^0x200 = swz(T(sigma(0x200))))
  __syncthreads();

  // ---- layer 0 closed form with CNOT folded in: a[i] = prod over bits of sigma(i) ----
  float a0, a1;
  {
    float tail = 1.f;
    #pragma unroll
    for (int q = 2; q < NQ; q++)
      tail *= ((sigTid >> (9 - q)) & 1) ? ps[q] : pc[q];
    const bool b9 = (sigTid >> 9) & 1, b8 = (sigTid >> 8) & 1;
    a0 = tail * (b9 ? ps[0] : pc[0]) * (b8 ? ps[1] : pc[1]);
    a1 = tail * (b9 ? pc[0] : ps[0]) * (b8 ? pc[1] : ps[1]);  // sigma(i^0x200)=sigma(i)^0x300
  }

  #pragma unroll
  for (int l = 1; l < NL; l++) {
    const float* C = pc + l * NQ;
    const float* S = ps + l * NQ;

    // layout A: RY wire 0 (k pair)
    {
      const float c0 = C[0], s0 = S[0];
      float t0 = a0, t1 = a1;
      a0 = c0 * t0 - s0 * t1;
      a1 = fmaf(s0, t0, c0 * t1);
    }
    // layout A: RY wires 5..9 (lane masks 16,8,4,2,1)
    #pragma unroll
    for (int q = 5; q < NQ; q++) {
      const int m = 1 << (9 - q);
      const float c = C[q];
      const float se = (lane & m) ? S[q] : -S[q];
      float p0 = __shfl_xor_sync(FULLM, a0, m);
      float p1 = __shfl_xor_sync(FULLM, a1, m);
      a0 = fmaf(c, a0, se * p0);
      a1 = fmaf(c, a1, se * p1);
    }
    // T round: A -> B
    bufA[sTid] = a0;  bufA[sTid ^ 0x210] = a1;
    __syncthreads();
    float b0 = bufA[sT5];
    float b1 = bufA[sT5 ^ 0x210];
    // layout B: RY wires 1..4 (lane masks 16,8,4,2)
    #pragma unroll
    for (int q = 1; q <= 4; q++) {
      const int m = 1 << (5 - q);
      const float c = C[q];
      const float se = (lane & m) ? S[q] : -S[q];
      float p0 = __shfl_xor_sync(FULLM, b0, m);
      float p1 = __shfl_xor_sync(FULLM, b1, m);
      b0 = fmaf(c, b0, se * p0);
      b1 = fmaf(c, b1, se * p1);
    }
    // tau round: B -> A with CNOT ring folded in (tau = T o sigma)
    bufB[sTid] = b0;  bufB[sTid ^ 0x210] = b1;
    __syncthreads();
    a0 = bufB[sTau];
    a1 = bufB[sTau ^ 0x200];
  }

  // ---- observables of base state (layout A) ----
  const float p0 = a0 * a0, p1 = a1 * a1;
  const float ptot = p0 + p1;

  // Z: Hadamard butterfly over lanes gives sum (v) + per-wire diffs (d5..d9) together
  float v = ptot, z0 = p0 - p1;
  float d5, d6, d7, d8v, d9;
  { float p = __shfl_xor_sync(FULLM, v, 16); d5 = v - p; v += p; }
  { d5 += __shfl_xor_sync(FULLM, d5, 8);
    float p = __shfl_xor_sync(FULLM, v, 8);  d6 = v - p; v += p; }
  { d5 += __shfl_xor_sync(FULLM, d5, 4); d6 += __shfl_xor_sync(FULLM, d6, 4);
    float p = __shfl_xor_sync(FULLM, v, 4);  d7 = v - p; v += p; }
  { d5 += __shfl_xor_sync(FULLM, d5, 2); d6 += __shfl_xor_sync(FULLM, d6, 2);
    d7 += __shfl_xor_sync(FULLM, d7, 2);
    float p = __shfl_xor_sync(FULLM, v, 2);  d8v = v - p; v += p; }
  { d5 += __shfl_xor_sync(FULLM, d5, 1); d6 += __shfl_xor_sync(FULLM, d6, 1);
    d7 += __shfl_xor_sync(FULLM, d7, 1); d8v += __shfl_xor_sync(FULLM, d8v, 1);
    float p = __shfl_xor_sync(FULLM, v, 1);  d9 = v - p; v += p; }
  #pragma unroll
  for (int m = 16; m >= 1; m >>= 1) z0 += __shfl_xor_sync(FULLM, z0, m);

  // X partials
  float xv[NQ];
  xv[0] = 2.f * a0 * a1;
  // wires 1..4: partners from bufB via tau-linearity: addr ^ swz(tau(m))
  xv[1] = fmaf(a0, bufB[sTau ^ 0x18],  a1 * bufB[(sTau ^ 0x200) ^ 0x18]);
  xv[2] = fmaf(a0, bufB[sTau ^ 0xC],   a1 * bufB[(sTau ^ 0x200) ^ 0xC]);
  xv[3] = fmaf(a0, bufB[sTau ^ 0x6],   a1 * bufB[(sTau ^ 0x200) ^ 0x6]);
  xv[4] = fmaf(a0, bufB[sTau ^ 0x10A], a1 * bufB[(sTau ^ 0x200) ^ 0x10A]);
  #pragma unroll
  for (int q = 5; q < NQ; q++) {
    const int m = 1 << (9 - q);
    xv[q] = fmaf(a0, __shfl_xor_sync(FULLM, a0, m),
                 a1 * __shfl_xor_sync(FULLM, a1, m));
  }
  #pragma unroll
  for (int q = 0; q < NQ; q++) {
    #pragma unroll
    for (int m = 16; m >= 1; m >>= 1) xv[q] += __shfl_xor_sync(FULLM, xv[q], m);
  }

  if (lane == 0) {
    r1[w][0] = v;  r1[w][1] = z0;
    r1[w][2] = d5; r1[w][3] = d6; r1[w][4] = d7; r1[w][5] = d8v; r1[w][6] = d9;
    #pragma unroll
    for (int q = 0; q < NQ; q++) r1[w][7 + q] = xv[q];
  }
  __syncthreads();
  if (tid < 20) {
    float s = 0.f;
    if (tid == 0) {
      #pragma unroll
      for (int i = 0; i < 16; i++) s += r1[i][1];
      zbs[0] = s;
    } else if (tid <= 4) {           // wires 1..4: sign is a per-warp bit
      #pragma unroll
      for (int i = 0; i < 16; i++)
        s += ((i >> (4 - tid)) & 1) ? -r1[i][0] : r1[i][0];
      zbs[tid] = s;
    } else if (tid <= 9) {           // wires 5..9 from butterfly diffs
      #pragma unroll
      for (int i = 0; i < 16; i++) s += r1[i][tid - 3];
      zbs[tid] = s;
    } else {
      #pragma unroll
      for (int i = 0; i < 16; i++) s += r1[i][7 + tid - 10];
      xbs[tid - 10] = s;
    }
  }
  __syncthreads();

  // ---- main: out[t][c] = (c<10) ? cos(x)*Zb[c] - sin(x)*Xb[c] : 0 ----
  const int total4 = nTok * 16;  // 16 float4 per 64-float token row
  const float4* __restrict__ x4 = (const float4*)x;
  float4* __restrict__ o4 = (float4*)out;
  for (int idx = blockIdx.x * blockDim.x + threadIdx.x; idx < total4;
       idx += gridDim.x * blockDim.x) {
    const int c4 = idx & 15;
    float4 o = make_float4(0.f, 0.f, 0.f, 0.f);
    if (c4 < 3) {
      const float4 xv4 = x4[idx];
      const int q0 = c4 * 4;
      float s0, c0, s1, c1;
      __sincosf(xv4.x, &s0, &c0); o.x = c0 * zbs[q0]     - s0 * xbs[q0];
      __sincosf(xv4.y, &s1, &c1); o.y = c1 * zbs[q0 + 1] - s1 * xbs[q0 + 1];
      if (c4 < 2) {
        float s2, c2, s3, c3;
        __sincosf(xv4.z, &s2, &c2); o.z = c2 * zbs[q0 + 2] - s2 * xbs[q0 + 2];
        __sincosf(xv4.w, &s3, &c3); o.w = c3 * zbs[q0 + 3] - s3 * xbs[q0 + 3];
      }
    }
    o4[idx] = o;
  }
}

extern "C" void kernel_launch(void* const* d_in, const int* in_sizes, int n_in,
                              void* d_out, int out_size) {
  const float* x = (const float*)d_in[0];
  const float* params = (const float*)d_in[1];
  if (n_in >= 2 && in_sizes[0] == NL * NQ) {   // robust to input ordering
    params = (const float*)d_in[0];
    x = (const float*)d_in[1];
  }
  const int nTok = out_size / 64;
  hqh_kernel<<<148, 512>>>(x, params, (float*)d_out, nTok);  // 1 block/SM
}